// round 3
// baseline (speedup 1.0000x reference)
#include <cuda_runtime.h>
#include <cuda_bf16.h>
#include <math.h>

// ---------------- problem constants ----------------
#define L_  6
#define B_  4
#define S_  512
#define D_  1024
#define H_  16
#define DK_ 64
#define DV_ 64
#define DFF_ 4096
#define M_  (B_ * S_)              // 2048 tokens

// ---------------- device scratch (allocation-free) ----------------
__device__ float g_x  [M_ * D_];
__device__ float g_q  [M_ * D_];
__device__ float g_k  [M_ * D_];
__device__ float g_v  [M_ * D_];
__device__ float g_ctx[M_ * D_];
__device__ float g_y  [M_ * D_];
__device__ float g_ffh[M_ * DFF_];
__device__ float g_sc [(size_t)B_ * H_ * S_ * S_];   // 64 MB scores scratch

// ---------------- embedding ----------------
__global__ void embed_kernel(const int* __restrict__ ids,
                             const float* __restrict__ tok,
                             const float* __restrict__ pos,
                             float* __restrict__ X) {
    int idx = blockIdx.x * 256 + threadIdx.x;    // over M_*256 float4 slots
    int m  = idx >> 8;
    int c  = (idx & 255) * 4;
    int s  = m & (S_ - 1);
    int id = ids[m];
    float4 t = *(const float4*)(tok + (size_t)id * D_ + c);
    float4 p = *(const float4*)(pos + (size_t)s  * D_ + c);
    t.x += p.x; t.y += p.y; t.z += p.z; t.w += p.w;
    *(float4*)(X + (size_t)m * D_ + c) = t;
}

// ---------------- fp32 SGEMM: C[M,N] = A[M,K] @ B[K,N], optional ReLU ----------------
// 128x128 tile, BK=8, 256 threads, 8x8 per thread. M,N %128==0, K %8==0.
template <int RELU>
__global__ void __launch_bounds__(256, 2)
sgemm_kernel(const float* __restrict__ A, const float* __restrict__ B,
             float* __restrict__ C, int M, int N, int K) {
    __shared__ float As[8][128];
    __shared__ float Bs[8][128];
    const int tid  = threadIdx.x;
    const int brow = blockIdx.y * 128;
    const int bcol = blockIdx.x * 128;

    const int aRow = tid >> 1;          // 0..127
    const int aCol = (tid & 1) * 4;     // 0 or 4
    const int bRow = tid >> 5;          // 0..7
    const int bCol = (tid & 31) * 4;    // 0..124

    const int tr = (tid >> 4) * 8;      // 0..120
    const int tc = (tid & 15) * 8;      // 0..120

    float acc[8][8];
#pragma unroll
    for (int i = 0; i < 8; i++)
#pragma unroll
        for (int j = 0; j < 8; j++) acc[i][j] = 0.f;

    for (int k0 = 0; k0 < K; k0 += 8) {
        float4 a4 = *(const float4*)(A + (size_t)(brow + aRow) * K + k0 + aCol);
        As[aCol + 0][aRow] = a4.x;
        As[aCol + 1][aRow] = a4.y;
        As[aCol + 2][aRow] = a4.z;
        As[aCol + 3][aRow] = a4.w;
        *(float4*)(&Bs[bRow][bCol]) =
            *(const float4*)(B + (size_t)(k0 + bRow) * N + bcol + bCol);
        __syncthreads();
#pragma unroll
        for (int kk = 0; kk < 8; kk++) {
            float ra[8], rb[8];
#pragma unroll
            for (int i = 0; i < 8; i++) ra[i] = As[kk][tr + i];
#pragma unroll
            for (int j = 0; j < 8; j++) rb[j] = Bs[kk][tc + j];
#pragma unroll
            for (int i = 0; i < 8; i++)
#pragma unroll
                for (int j = 0; j < 8; j++) acc[i][j] += ra[i] * rb[j];
        }
        __syncthreads();
    }

#pragma unroll
    for (int i = 0; i < 8; i++) {
#pragma unroll
        for (int j = 0; j < 8; j += 4) {
            float4 v;
            v.x = acc[i][j+0]; v.y = acc[i][j+1]; v.z = acc[i][j+2]; v.w = acc[i][j+3];
            if (RELU) {
                v.x = fmaxf(v.x, 0.f); v.y = fmaxf(v.y, 0.f);
                v.z = fmaxf(v.z, 0.f); v.w = fmaxf(v.w, 0.f);
            }
            *(float4*)(C + (size_t)(brow + tr + i) * N + bcol + tc + j) = v;
        }
    }
}

// ---------------- QK^T (scale + optional pad|causal mask) ----------------
// grid (S/64, S/64, B*H), 256 threads, 64x64 output tile, 4x4 per thread.
template <bool MASKED>
__global__ void __launch_bounds__(256)
qk_kernel(const float* __restrict__ Q, const float* __restrict__ K,
          const int* __restrict__ ids, float* __restrict__ S_out) {
    const int bh = blockIdx.z;
    const int b  = bh / H_;
    const int h  = bh % H_;
    const int q0 = blockIdx.y * 64;
    const int k0 = blockIdx.x * 64;

    __shared__ float Qs[64][68];
    __shared__ float Ks[64][68];

    const int tid = threadIdx.x;
    const float* Qb = Q + ((size_t)(b * S_ + q0)) * D_ + h * DK_;
    const float* Kb = K + ((size_t)(b * S_ + k0)) * D_ + h * DK_;

#pragma unroll
    for (int it = 0; it < 4; it++) {
        int idx = tid + it * 256;        // 0..1023
        int row = idx >> 4;              // 0..63
        int c4  = (idx & 15) * 4;        // 0..60
        *(float4*)(&Qs[row][c4]) = *(const float4*)(Qb + (size_t)row * D_ + c4);
        *(float4*)(&Ks[row][c4]) = *(const float4*)(Kb + (size_t)row * D_ + c4);
    }
    __syncthreads();

    const int tq = (tid >> 4) * 4;
    const int tk = (tid & 15) * 4;
    float acc[4][4];
#pragma unroll
    for (int i = 0; i < 4; i++)
#pragma unroll
        for (int j = 0; j < 4; j++) acc[i][j] = 0.f;

#pragma unroll 16
    for (int kk = 0; kk < 64; kk++) {
        float rq[4], rk[4];
#pragma unroll
        for (int i = 0; i < 4; i++) rq[i] = Qs[tq + i][kk];
#pragma unroll
        for (int j = 0; j < 4; j++) rk[j] = Ks[tk + j][kk];
#pragma unroll
        for (int i = 0; i < 4; i++)
#pragma unroll
            for (int j = 0; j < 4; j++) acc[i][j] += rq[i] * rk[j];
    }

    float* Sb = S_out + ((size_t)bh * S_ + q0) * S_ + k0;
#pragma unroll
    for (int i = 0; i < 4; i++) {
#pragma unroll
        for (int j = 0; j < 4; j++) {
            int q = q0 + tq + i;
            int k = k0 + tk + j;
            float val = acc[i][j] * 0.125f;     // 1/sqrt(64)
            if (MASKED) {
                bool m = (ids[b * S_ + k] == 0) || (k > q);
                if (m) val = -1e9f;
            }
            Sb[(size_t)(tq + i) * S_ + tk + j] = val;
        }
    }
}

// ---------------- row softmax over 512 (in place) ----------------
__global__ void __launch_bounds__(128)
softmax_kernel(float* __restrict__ P) {
    float* p = P + (size_t)blockIdx.x * S_;
    const int tid = threadIdx.x;                 // 128 threads, 4 elems each
    float4 v = *(float4*)(p + tid * 4);

    float m = fmaxf(fmaxf(v.x, v.y), fmaxf(v.z, v.w));
#pragma unroll
    for (int o = 16; o; o >>= 1) m = fmaxf(m, __shfl_xor_sync(0xffffffffu, m, o));
    __shared__ float sm[4];
    if ((tid & 31) == 0) sm[tid >> 5] = m;
    __syncthreads();
    m = fmaxf(fmaxf(sm[0], sm[1]), fmaxf(sm[2], sm[3]));

    v.x = expf(v.x - m); v.y = expf(v.y - m);
    v.z = expf(v.z - m); v.w = expf(v.w - m);
    float s = v.x + v.y + v.z + v.w;
#pragma unroll
    for (int o = 16; o; o >>= 1) s += __shfl_xor_sync(0xffffffffu, s, o);
    __shared__ float ss[4];
    if ((tid & 31) == 0) ss[tid >> 5] = s;
    __syncthreads();
    s = ss[0] + ss[1] + ss[2] + ss[3];

    float inv = 1.0f / s;
    v.x *= inv; v.y *= inv; v.z *= inv; v.w *= inv;
    *(float4*)(p + tid * 4) = v;
}

// ---------------- attn @ V : ctx[b,q,h*64+d] ----------------
// grid (S/64, 1, B*H), 256 threads, 64(q) x 64(d) tile, K loop over 512.
__global__ void __launch_bounds__(256)
av_kernel(const float* __restrict__ P, const float* __restrict__ V,
          float* __restrict__ C) {
    const int bh = blockIdx.z;
    const int b  = bh / H_;
    const int h  = bh % H_;
    const int q0 = blockIdx.x * 64;

    __shared__ float Ps[64][68];
    __shared__ float Vs[64][68];

    const int tid = threadIdx.x;
    const float* Pb = P + ((size_t)bh * S_ + q0) * S_;
    const float* Vb = V + ((size_t)(b * S_)) * D_ + h * DV_;

    const int tq = (tid >> 4) * 4;
    const int td = (tid & 15) * 4;
    float acc[4][4];
#pragma unroll
    for (int i = 0; i < 4; i++)
#pragma unroll
        for (int j = 0; j < 4; j++) acc[i][j] = 0.f;

    for (int kc = 0; kc < S_; kc += 64) {
#pragma unroll
        for (int it = 0; it < 4; it++) {
            int idx = tid + it * 256;
            int row = idx >> 4;
            int c4  = (idx & 15) * 4;
            *(float4*)(&Ps[row][c4]) = *(const float4*)(Pb + (size_t)row * S_ + kc + c4);
            *(float4*)(&Vs[row][c4]) = *(const float4*)(Vb + (size_t)(kc + row) * D_ + c4);
        }
        __syncthreads();
#pragma unroll 16
        for (int kk = 0; kk < 64; kk++) {
            float rp[4], rv[4];
#pragma unroll
            for (int i = 0; i < 4; i++) rp[i] = Ps[tq + i][kk];
#pragma unroll
            for (int j = 0; j < 4; j++) rv[j] = Vs[kk][td + j];
#pragma unroll
            for (int i = 0; i < 4; i++)
#pragma unroll
                for (int j = 0; j < 4; j++) acc[i][j] += rp[i] * rv[j];
        }
        __syncthreads();
    }

#pragma unroll
    for (int i = 0; i < 4; i++)
#pragma unroll
        for (int j = 0; j < 4; j++)
            C[(size_t)(b * S_ + q0 + tq + i) * D_ + h * DV_ + td + j] = acc[i][j];
}

// ---------------- fused residual + LayerNorm, writes back to X ----------------
__global__ void __launch_bounds__(256)
add_ln_kernel(const float* __restrict__ Y, float* __restrict__ X,
              const float* __restrict__ g, const float* __restrict__ bb) {
    const int row = blockIdx.x;
    const int tid = threadIdx.x;                 // 256 threads, 1 float4 each
    const float4* y4 = (const float4*)(Y + (size_t)row * D_);
    float4*       x4 = (float4*)(X + (size_t)row * D_);

    float4 v  = y4[tid];
    float4 xr = x4[tid];
    v.x += xr.x; v.y += xr.y; v.z += xr.z; v.w += xr.w;

    float s  = v.x + v.y + v.z + v.w;
    float sq = v.x*v.x + v.y*v.y + v.z*v.z + v.w*v.w;
#pragma unroll
    for (int o = 16; o; o >>= 1) {
        s  += __shfl_xor_sync(0xffffffffu, s,  o);
        sq += __shfl_xor_sync(0xffffffffu, sq, o);
    }
    __shared__ float s_s[8], s_q[8];
    if ((tid & 31) == 0) { s_s[tid >> 5] = s; s_q[tid >> 5] = sq; }
    __syncthreads();
    s = 0.f; sq = 0.f;
#pragma unroll
    for (int w = 0; w < 8; w++) { s += s_s[w]; sq += s_q[w]; }

    const float mean = s * (1.0f / D_);
    const float var  = sq * (1.0f / D_) - mean * mean;
    const float rstd = rsqrtf(var + 1e-5f);

    float4 gv = ((const float4*)g)[tid];
    float4 bv = ((const float4*)bb)[tid];
    v.x = (v.x - mean) * rstd * gv.x + bv.x;
    v.y = (v.y - mean) * rstd * gv.y + bv.y;
    v.z = (v.z - mean) * rstd * gv.z + bv.z;
    v.w = (v.w - mean) * rstd * gv.w + bv.w;
    x4[tid] = v;
}

// ---------------- final copy x -> out ----------------
__global__ void copy_kernel(const float* __restrict__ src, float* __restrict__ dst) {
    int idx = blockIdx.x * 256 + threadIdx.x;
    ((float4*)dst)[idx] = ((const float4*)src)[idx];
}

// ---------------- host orchestration ----------------
static inline void run_gemm(const float* A, const float* B, float* C,
                            int M, int N, int K, bool relu) {
    dim3 grid(N / 128, M / 128);
    if (relu) sgemm_kernel<1><<<grid, 256>>>(A, B, C, M, N, K);
    else      sgemm_kernel<0><<<grid, 256>>>(A, B, C, M, N, K);
}

extern "C" void kernel_launch(void* const* d_in, const int* in_sizes, int n_in,
                              void* d_out, int out_size) {
    const int*   ids = (const int*)  d_in[0];
    const float* tok = (const float*)d_in[1];
    const float* pos = (const float*)d_in[2];
    const float* Wq1 = (const float*)d_in[3];
    const float* Wk1 = (const float*)d_in[4];
    const float* Wv1 = (const float*)d_in[5];
    const float* Wo1 = (const float*)d_in[6];
    const float* g1  = (const float*)d_in[7];
    const float* b1  = (const float*)d_in[8];
    const float* Wq2 = (const float*)d_in[9];
    const float* Wk2 = (const float*)d_in[10];
    const float* Wv2 = (const float*)d_in[11];
    const float* Wo2 = (const float*)d_in[12];
    const float* g2  = (const float*)d_in[13];
    const float* b2  = (const float*)d_in[14];
    const float* Wff1= (const float*)d_in[15];
    const float* Wff2= (const float*)d_in[16];
    const float* gff = (const float*)d_in[17];
    const float* bff = (const float*)d_in[18];
    float* out = (float*)d_out;

    float *x, *q, *k, *v, *ctx, *y, *ffh, *sc;
    cudaGetSymbolAddress((void**)&x,   g_x);
    cudaGetSymbolAddress((void**)&q,   g_q);
    cudaGetSymbolAddress((void**)&k,   g_k);
    cudaGetSymbolAddress((void**)&v,   g_v);
    cudaGetSymbolAddress((void**)&ctx, g_ctx);
    cudaGetSymbolAddress((void**)&y,   g_y);
    cudaGetSymbolAddress((void**)&ffh, g_ffh);
    cudaGetSymbolAddress((void**)&sc,  g_sc);

    const size_t xsz  = (size_t)M_ * D_;                 // 2,097,152
    const size_t asz  = (size_t)B_ * H_ * S_ * S_;       // 16,777,216 per layer
    const bool   full = ((size_t)out_size >= xsz + (size_t)L_ * asz);

    // embedding
    embed_kernel<<<M_ * (D_ / 4) / 256, 256>>>(ids, tok, pos, x);

    const dim3 qk_grid(S_ / 64, S_ / 64, B_ * H_);
    const dim3 av_grid(S_ / 64, 1,       B_ * H_);
    const int  sm_rows = B_ * H_ * S_;                   // 131072 softmax rows

    for (int i = 0; i < L_; i++) {
        const size_t wA = (size_t)i * D_ * (H_ * DK_);   // D x 1024 weights
        const size_t wF1 = (size_t)i * D_ * DFF_;
        const size_t wF2 = (size_t)i * DFF_ * D_;
        const size_t wG = (size_t)i * D_;

        // -------- MHA1 (masked) --------
        run_gemm(x, Wq1 + wA, q, M_, H_ * DK_, D_, false);
        run_gemm(x, Wk1 + wA, k, M_, H_ * DK_, D_, false);
        run_gemm(x, Wv1 + wA, v, M_, H_ * DV_, D_, false);
        qk_kernel<true><<<qk_grid, 256>>>(q, k, ids, sc);
        softmax_kernel<<<sm_rows, 128>>>(sc);
        av_kernel<<<av_grid, 256>>>(sc, v, ctx);
        run_gemm(ctx, Wo1 + wA, y, M_, D_, H_ * DV_, false);
        add_ln_kernel<<<M_, 256>>>(y, x, g1 + wG, b1 + wG);

        // -------- MHA2 (unmasked, attn saved) --------
        float* att = full ? (out + xsz + (size_t)i * asz) : sc;
        run_gemm(x, Wq2 + wA, q, M_, H_ * DK_, D_, false);
        run_gemm(x, Wk2 + wA, k, M_, H_ * DK_, D_, false);
        run_gemm(x, Wv2 + wA, v, M_, H_ * DV_, D_, false);
        qk_kernel<false><<<qk_grid, 256>>>(q, k, nullptr, att);
        softmax_kernel<<<sm_rows, 128>>>(att);
        av_kernel<<<av_grid, 256>>>(att, v, ctx);
        run_gemm(ctx, Wo2 + wA, y, M_, D_, H_ * DV_, false);
        add_ln_kernel<<<M_, 256>>>(y, x, g2 + wG, b2 + wG);

        // -------- FFN --------
        run_gemm(x, Wff1 + wF1, ffh, M_, DFF_, D_, true);   // fused ReLU
        run_gemm(ffh, Wff2 + wF2, y, M_, D_, DFF_, false);
        add_ln_kernel<<<M_, 256>>>(y, x, gff + wG, bff + wG);
    }

    // final x -> out[0 : B*S*D)
    copy_kernel<<<(int)(xsz / 4 / 256), 256>>>(x, out);
}

// round 5
// speedup vs baseline: 1.5132x; 1.5132x over previous
#include <cuda_runtime.h>
#include <cuda_bf16.h>
#include <math.h>

// ---------------- problem constants ----------------
#define L_  6
#define B_  4
#define S_  512
#define D_  1024
#define H_  16
#define DK_ 64
#define DV_ 64
#define DFF_ 4096
#define M_  (B_ * S_)              // 2048 tokens

// ---------------- device scratch (allocation-free) ----------------
__device__ float g_x  [M_ * D_];
__device__ float g_q  [M_ * D_];
__device__ float g_k  [M_ * D_];
__device__ float g_v  [M_ * D_];
__device__ float g_ctx[M_ * D_];
__device__ float g_y  [M_ * D_];
__device__ float g_ffh[M_ * DFF_];
__device__ float g_sc [(size_t)B_ * H_ * S_ * S_];   // 64 MB scores scratch

// ---------------- embedding ----------------
__global__ void embed_kernel(const int* __restrict__ ids,
                             const float* __restrict__ tok,
                             const float* __restrict__ pos,
                             float* __restrict__ X) {
    int idx = blockIdx.x * 256 + threadIdx.x;    // over M_*256 float4 slots
    int m  = idx >> 8;
    int c  = (idx & 255) * 4;
    int s  = m & (S_ - 1);
    int id = ids[m];
    float4 t = *(const float4*)(tok + (size_t)id * D_ + c);
    float4 p = *(const float4*)(pos + (size_t)s  * D_ + c);
    t.x += p.x; t.y += p.y; t.z += p.z; t.w += p.w;
    *(float4*)(X + (size_t)m * D_ + c) = t;
}

// ---------------- fp32 SGEMM: C[M,N] = A[M,K] @ B[K,N], optional ReLU ----------------
// 128x128 tile, BK=8, 256 threads, 8x8 per thread. M,N %128==0, K %8==0.
template <int RELU>
__global__ void __launch_bounds__(256, 2)
sgemm_kernel(const float* __restrict__ A, const float* __restrict__ B,
             float* __restrict__ C, int M, int N, int K) {
    __shared__ float As[8][128];
    __shared__ float Bs[8][128];
    const int tid  = threadIdx.x;
    const int brow = blockIdx.y * 128;
    const int bcol = blockIdx.x * 128;

    const int aRow = tid >> 1;          // 0..127
    const int aCol = (tid & 1) * 4;     // 0 or 4
    const int bRow = tid >> 5;          // 0..7
    const int bCol = (tid & 31) * 4;    // 0..124

    const int tr = (tid >> 4) * 8;      // 0..120
    const int tc = (tid & 15) * 8;      // 0..120

    float acc[8][8];
#pragma unroll
    for (int i = 0; i < 8; i++)
#pragma unroll
        for (int j = 0; j < 8; j++) acc[i][j] = 0.f;

    for (int k0 = 0; k0 < K; k0 += 8) {
        float4 a4 = *(const float4*)(A + (size_t)(brow + aRow) * K + k0 + aCol);
        As[aCol + 0][aRow] = a4.x;
        As[aCol + 1][aRow] = a4.y;
        As[aCol + 2][aRow] = a4.z;
        As[aCol + 3][aRow] = a4.w;
        *(float4*)(&Bs[bRow][bCol]) =
            *(const float4*)(B + (size_t)(k0 + bRow) * N + bcol + bCol);
        __syncthreads();
#pragma unroll
        for (int kk = 0; kk < 8; kk++) {
            float ra[8], rb[8];
#pragma unroll
            for (int i = 0; i < 8; i++) ra[i] = As[kk][tr + i];
#pragma unroll
            for (int j = 0; j < 8; j++) rb[j] = Bs[kk][tc + j];
#pragma unroll
            for (int i = 0; i < 8; i++)
#pragma unroll
                for (int j = 0; j < 8; j++) acc[i][j] += ra[i] * rb[j];
        }
        __syncthreads();
    }

#pragma unroll
    for (int i = 0; i < 8; i++) {
#pragma unroll
        for (int j = 0; j < 8; j += 4) {
            float4 v;
            v.x = acc[i][j+0]; v.y = acc[i][j+1]; v.z = acc[i][j+2]; v.w = acc[i][j+3];
            if (RELU) {
                v.x = fmaxf(v.x, 0.f); v.y = fmaxf(v.y, 0.f);
                v.z = fmaxf(v.z, 0.f); v.w = fmaxf(v.w, 0.f);
            }
            *(float4*)(C + (size_t)(brow + tr + i) * N + bcol + tc + j) = v;
        }
    }
}

// ---------------- QK^T (scale + optional pad|causal mask) ----------------
// grid (S/64, S/64, B*H), 256 threads, 64x64 output tile, 4x4 per thread.
template <bool MASKED>
__global__ void __launch_bounds__(256)
qk_kernel(const float* __restrict__ Q, const float* __restrict__ K,
          const int* __restrict__ ids, float* __restrict__ S_out) {
    const int bh = blockIdx.z;
    const int b  = bh / H_;
    const int h  = bh % H_;
    const int q0 = blockIdx.y * 64;
    const int k0 = blockIdx.x * 64;

    __shared__ float Qs[64][68];
    __shared__ float Ks[64][68];

    const int tid = threadIdx.x;
    const float* Qb = Q + ((size_t)(b * S_ + q0)) * D_ + h * DK_;
    const float* Kb = K + ((size_t)(b * S_ + k0)) * D_ + h * DK_;

#pragma unroll
    for (int it = 0; it < 4; it++) {
        int idx = tid + it * 256;        // 0..1023
        int row = idx >> 4;              // 0..63
        int c4  = (idx & 15) * 4;        // 0..60
        *(float4*)(&Qs[row][c4]) = *(const float4*)(Qb + (size_t)row * D_ + c4);
        *(float4*)(&Ks[row][c4]) = *(const float4*)(Kb + (size_t)row * D_ + c4);
    }
    __syncthreads();

    const int tq = (tid >> 4) * 4;
    const int tk = (tid & 15) * 4;
    float acc[4][4];
#pragma unroll
    for (int i = 0; i < 4; i++)
#pragma unroll
        for (int j = 0; j < 4; j++) acc[i][j] = 0.f;

#pragma unroll 16
    for (int kk = 0; kk < 64; kk++) {
        float rq[4], rk[4];
#pragma unroll
        for (int i = 0; i < 4; i++) rq[i] = Qs[tq + i][kk];
#pragma unroll
        for (int j = 0; j < 4; j++) rk[j] = Ks[tk + j][kk];
#pragma unroll
        for (int i = 0; i < 4; i++)
#pragma unroll
            for (int j = 0; j < 4; j++) acc[i][j] += rq[i] * rk[j];
    }

    float* Sb = S_out + ((size_t)bh * S_ + q0) * S_ + k0;
#pragma unroll
    for (int i = 0; i < 4; i++) {
#pragma unroll
        for (int j = 0; j < 4; j++) {
            int q = q0 + tq + i;
            int k = k0 + tk + j;
            float val = acc[i][j] * 0.125f;     // 1/sqrt(64)
            if (MASKED) {
                bool m = (ids[b * S_ + k] == 0) || (k > q);
                if (m) val = -1e9f;
            }
            Sb[(size_t)(tq + i) * S_ + tk + j] = val;
        }
    }
}

// ---------------- row softmax over 512 (in place) ----------------
__global__ void __launch_bounds__(128)
softmax_kernel(float* __restrict__ P) {
    float* p = P + (size_t)blockIdx.x * S_;
    const int tid = threadIdx.x;                 // 128 threads, 4 elems each
    float4 v = *(float4*)(p + tid * 4);

    float m = fmaxf(fmaxf(v.x, v.y), fmaxf(v.z, v.w));
#pragma unroll
    for (int o = 16; o; o >>= 1) m = fmaxf(m, __shfl_xor_sync(0xffffffffu, m, o));
    __shared__ float sm[4];
    if ((tid & 31) == 0) sm[tid >> 5] = m;
    __syncthreads();
    m = fmaxf(fmaxf(sm[0], sm[1]), fmaxf(sm[2], sm[3]));

    v.x = expf(v.x - m); v.y = expf(v.y - m);
    v.z = expf(v.z - m); v.w = expf(v.w - m);
    float s = v.x + v.y + v.z + v.w;
#pragma unroll
    for (int o = 16; o; o >>= 1) s += __shfl_xor_sync(0xffffffffu, s, o);
    __shared__ float ss[4];
    if ((tid & 31) == 0) ss[tid >> 5] = s;
    __syncthreads();
    s = ss[0] + ss[1] + ss[2] + ss[3];

    float inv = 1.0f / s;
    v.x *= inv; v.y *= inv; v.z *= inv; v.w *= inv;
    *(float4*)(p + tid * 4) = v;
}

// ---------------- attn @ V : ctx[b,q,h*64+d] ----------------
// grid (S/64, 1, B*H), 256 threads, 64(q) x 64(d) tile, K loop over 512.
__global__ void __launch_bounds__(256)
av_kernel(const float* __restrict__ P, const float* __restrict__ V,
          float* __restrict__ C) {
    const int bh = blockIdx.z;
    const int b  = bh / H_;
    const int h  = bh % H_;
    const int q0 = blockIdx.x * 64;

    __shared__ float Ps[64][68];
    __shared__ float Vs[64][68];

    const int tid = threadIdx.x;
    const float* Pb = P + ((size_t)bh * S_ + q0) * S_;
    const float* Vb = V + ((size_t)(b * S_)) * D_ + h * DV_;

    const int tq = (tid >> 4) * 4;
    const int td = (tid & 15) * 4;
    float acc[4][4];
#pragma unroll
    for (int i = 0; i < 4; i++)
#pragma unroll
        for (int j = 0; j < 4; j++) acc[i][j] = 0.f;

    for (int kc = 0; kc < S_; kc += 64) {
#pragma unroll
        for (int it = 0; it < 4; it++) {
            int idx = tid + it * 256;
            int row = idx >> 4;
            int c4  = (idx & 15) * 4;
            *(float4*)(&Ps[row][c4]) = *(const float4*)(Pb + (size_t)row * S_ + kc + c4);
            *(float4*)(&Vs[row][c4]) = *(const float4*)(Vb + (size_t)(kc + row) * D_ + c4);
        }
        __syncthreads();
#pragma unroll 16
        for (int kk = 0; kk < 64; kk++) {
            float rp[4], rv[4];
#pragma unroll
            for (int i = 0; i < 4; i++) rp[i] = Ps[tq + i][kk];
#pragma unroll
            for (int j = 0; j < 4; j++) rv[j] = Vs[kk][td + j];
#pragma unroll
            for (int i = 0; i < 4; i++)
#pragma unroll
                for (int j = 0; j < 4; j++) acc[i][j] += rp[i] * rv[j];
        }
        __syncthreads();
    }

#pragma unroll
    for (int i = 0; i < 4; i++)
#pragma unroll
        for (int j = 0; j < 4; j++)
            C[(size_t)(b * S_ + q0 + tq + i) * D_ + h * DV_ + td + j] = acc[i][j];
}

// ---------------- fused residual + LayerNorm, writes back to X ----------------
__global__ void __launch_bounds__(256)
add_ln_kernel(const float* __restrict__ Y, float* __restrict__ X,
              const float* __restrict__ g, const float* __restrict__ bb) {
    const int row = blockIdx.x;
    const int tid = threadIdx.x;                 // 256 threads, 1 float4 each
    const float4* y4 = (const float4*)(Y + (size_t)row * D_);
    float4*       x4 = (float4*)(X + (size_t)row * D_);

    float4 v  = y4[tid];
    float4 xr = x4[tid];
    v.x += xr.x; v.y += xr.y; v.z += xr.z; v.w += xr.w;

    float s  = v.x + v.y + v.z + v.w;
    float sq = v.x*v.x + v.y*v.y + v.z*v.z + v.w*v.w;
#pragma unroll
    for (int o = 16; o; o >>= 1) {
        s  += __shfl_xor_sync(0xffffffffu, s,  o);
        sq += __shfl_xor_sync(0xffffffffu, sq, o);
    }
    __shared__ float s_s[8], s_q[8];
    if ((tid & 31) == 0) { s_s[tid >> 5] = s; s_q[tid >> 5] = sq; }
    __syncthreads();
    s = 0.f; sq = 0.f;
#pragma unroll
    for (int w = 0; w < 8; w++) { s += s_s[w]; sq += s_q[w]; }

    const float mean = s * (1.0f / D_);
    const float var  = sq * (1.0f / D_) - mean * mean;
    const float rstd = rsqrtf(var + 1e-5f);

    float4 gv = ((const float4*)g)[tid];
    float4 bv = ((const float4*)bb)[tid];
    v.x = (v.x - mean) * rstd * gv.x + bv.x;
    v.y = (v.y - mean) * rstd * gv.y + bv.y;
    v.z = (v.z - mean) * rstd * gv.z + bv.z;
    v.w = (v.w - mean) * rstd * gv.w + bv.w;
    x4[tid] = v;
}

// ---------------- final copy x -> out ----------------
__global__ void copy_kernel(const float* __restrict__ src, float* __restrict__ dst) {
    int idx = blockIdx.x * 256 + threadIdx.x;
    ((float4*)dst)[idx] = ((const float4*)src)[idx];
}

// ---------------- host orchestration ----------------
static inline void run_gemm(const float* A, const float* B, float* C,
                            int M, int N, int K, bool relu) {
    dim3 grid(N / 128, M / 128);
    if (relu) sgemm_kernel<1><<<grid, 256>>>(A, B, C, M, N, K);
    else      sgemm_kernel<0><<<grid, 256>>>(A, B, C, M, N, K);
}

extern "C" void kernel_launch(void* const* d_in, const int* in_sizes, int n_in,
                              void* d_out, int out_size) {
    const int*   ids = (const int*)  d_in[0];
    const float* tok = (const float*)d_in[1];
    const float* pos = (const float*)d_in[2];
    const float* Wq1 = (const float*)d_in[3];
    const float* Wk1 = (const float*)d_in[4];
    const float* Wv1 = (const float*)d_in[5];
    const float* Wo1 = (const float*)d_in[6];
    const float* g1  = (const float*)d_in[7];
    const float* b1  = (const float*)d_in[8];
    const float* Wq2 = (const float*)d_in[9];
    const float* Wk2 = (const float*)d_in[10];
    const float* Wv2 = (const float*)d_in[11];
    const float* Wo2 = (const float*)d_in[12];
    const float* g2  = (const float*)d_in[13];
    const float* b2  = (const float*)d_in[14];
    const float* Wff1= (const float*)d_in[15];
    const float* Wff2= (const float*)d_in[16];
    const float* gff = (const float*)d_in[17];
    const float* bff = (const float*)d_in[18];
    float* out = (float*)d_out;

    float *x, *q, *k, *v, *ctx, *y, *ffh, *sc;
    cudaGetSymbolAddress((void**)&x,   g_x);
    cudaGetSymbolAddress((void**)&q,   g_q);
    cudaGetSymbolAddress((void**)&k,   g_k);
    cudaGetSymbolAddress((void**)&v,   g_v);
    cudaGetSymbolAddress((void**)&ctx, g_ctx);
    cudaGetSymbolAddress((void**)&y,   g_y);
    cudaGetSymbolAddress((void**)&ffh, g_ffh);
    cudaGetSymbolAddress((void**)&sc,  g_sc);

    const size_t xsz  = (size_t)M_ * D_;                 // 2,097,152
    const size_t asz  = (size_t)B_ * H_ * S_ * S_;       // 16,777,216 per layer
    const bool   full = ((size_t)out_size >= xsz + (size_t)L_ * asz);

    // embedding
    embed_kernel<<<M_ * (D_ / 4) / 256, 256>>>(ids, tok, pos, x);

    const dim3 qk_grid(S_ / 64, S_ / 64, B_ * H_);
    const dim3 av_grid(S_ / 64, 1,       B_ * H_);
    const int  sm_rows = B_ * H_ * S_;                   // 131072 softmax rows

    for (int i = 0; i < L_; i++) {
        const size_t wA = (size_t)i * D_ * (H_ * DK_);   // D x 1024 weights
        const size_t wF1 = (size_t)i * D_ * DFF_;
        const size_t wF2 = (size_t)i * DFF_ * D_;
        const size_t wG = (size_t)i * D_;

        // -------- MHA1 (masked) --------
        run_gemm(x, Wq1 + wA, q, M_, H_ * DK_, D_, false);
        run_gemm(x, Wk1 + wA, k, M_, H_ * DK_, D_, false);
        run_gemm(x, Wv1 + wA, v, M_, H_ * DV_, D_, false);
        qk_kernel<true><<<qk_grid, 256>>>(q, k, ids, sc);
        softmax_kernel<<<sm_rows, 128>>>(sc);
        av_kernel<<<av_grid, 256>>>(sc, v, ctx);
        run_gemm(ctx, Wo1 + wA, y, M_, D_, H_ * DV_, false);
        add_ln_kernel<<<M_, 256>>>(y, x, g1 + wG, b1 + wG);

        // -------- MHA2 (unmasked, attn saved) --------
        float* att = full ? (out + xsz + (size_t)i * asz) : sc;
        run_gemm(x, Wq2 + wA, q, M_, H_ * DK_, D_, false);
        run_gemm(x, Wk2 + wA, k, M_, H_ * DK_, D_, false);
        run_gemm(x, Wv2 + wA, v, M_, H_ * DV_, D_, false);
        qk_kernel<false><<<qk_grid, 256>>>(q, k, nullptr, att);
        softmax_kernel<<<sm_rows, 128>>>(att);
        av_kernel<<<av_grid, 256>>>(att, v, ctx);
        run_gemm(ctx, Wo2 + wA, y, M_, D_, H_ * DV_, false);
        add_ln_kernel<<<M_, 256>>>(y, x, g2 + wG, b2 + wG);

        // -------- FFN --------
        run_gemm(x, Wff1 + wF1, ffh, M_, DFF_, D_, true);   // fused ReLU
        run_gemm(ffh, Wff2 + wF2, y, M_, D_, DFF_, false);
        add_ln_kernel<<<M_, 256>>>(y, x, gff + wG, bff + wG);
    }

    // final x -> out[0 : B*S*D)
    copy_kernel<<<(int)(xsz / 4 / 256), 256>>>(x, out);
}